// round 4
// baseline (speedup 1.0000x reference)
#include <cuda_runtime.h>
#include <math.h>

// GenomicLogicBraidIntegrator — single launch, latency-optimized.
//
// r2[j] takes only 4 distinct values -> (dr2[j], m2[j]) determined by
// (idx[j], idx[j+1]) -> 16 segment descriptors. O(N^2) Gauss linking sum
// collapses EXACTLY to sum_i sum_{g<16} count[g] * term(i,g).
//
// This version removes the two serial latency chains found in ncu:
//  * all global loads (idx as int4 x8, bytes) issued up-front -> 1 DRAM trip
//  * histogram via packed per-thread counters + shuffle reduce (no atomics)

#define EPSF 1e-9f
#define NBLK 32
#define NTHR 128
#define PERT 32          // idx elements per thread (NTHR*PERT = 4096)

__device__ double       g_partial[NBLK];
__device__ unsigned int g_ticket = 0;

__global__ void __launch_bounds__(NTHR)
braid_fused_kernel(const float* __restrict__ bytes,
                   const int*   __restrict__ idx,
                   int n, float* __restrict__ out)
{
    const int tid  = threadIdx.x;
    const int lane = tid & 31;
    const int wid  = tid >> 5;
    const int nseg = n - 1;                 // 4095

    // =====================================================================
    // Phase 0: issue ALL global loads up front (max MLP, one DRAM trip)
    // =====================================================================
    const int base = tid * PERT;            // 16B-aligned (32 ints)
    int4 v4[PERT / 4];
    const int4* idx4 = (const int4*)(idx + base);
    #pragma unroll
    for (int k = 0; k < PERT / 4; k++) v4[k] = idx4[k];
    int v32 = (base + PERT < n) ? idx[base + PERT] : 0;

    const int i = blockIdx.x * NTHR + tid;
    float b0 = (i < n)    ? bytes[i]     : 0.0f;
    float b1 = (i < nseg) ? bytes[i + 1] : 0.0f;

    // =====================================================================
    // Phase 1: atomic-free 16-bin histogram of (idx[j], idx[j+1])
    //   4 x u64 packed counters: bin g lives in acc[g>>2], field (g&3)*16.
    //   per-thread <= 32, per-warp <= 1024 -> 16-bit fields never overflow.
    // =====================================================================
    int v[PERT + 1];
    #pragma unroll
    for (int k = 0; k < PERT / 4; k++) {
        v[k * 4 + 0] = v4[k].x; v[k * 4 + 1] = v4[k].y;
        v[k * 4 + 2] = v4[k].z; v[k * 4 + 3] = v4[k].w;
    }
    v[PERT] = v32;

    unsigned long long acc0 = 0, acc1 = 0, acc2 = 0, acc3 = 0;
    #pragma unroll
    for (int k = 0; k < PERT; k++) {
        if (base + k < nseg) {
            int g  = (v[k] << 2) | v[k + 1];
            unsigned long long inc = 1ULL << ((g & 3) * 16);
            switch (g >> 2) {
                case 0: acc0 += inc; break;
                case 1: acc1 += inc; break;
                case 2: acc2 += inc; break;
                default: acc3 += inc; break;
            }
        }
    }

    // warp tree-reduce the 4 packed accumulators
    #pragma unroll
    for (int off = 16; off > 0; off >>= 1) {
        acc0 += __shfl_down_sync(0xffffffffu, acc0, off);
        acc1 += __shfl_down_sync(0xffffffffu, acc1, off);
        acc2 += __shfl_down_sync(0xffffffffu, acc2, off);
        acc3 += __shfl_down_sync(0xffffffffu, acc3, off);
    }

    __shared__ unsigned long long warp_acc[4][4];
    if (lane == 0) {
        warp_acc[wid][0] = acc0; warp_acc[wid][1] = acc1;
        warp_acc[wid][2] = acc2; warp_acc[wid][3] = acc3;
    }

    __shared__ float s_cnt[16];
    __shared__ float s_dr2[16][3];
    __shared__ float s_m2 [16][3];
    __syncthreads();

    if (tid < 16) {
        int q  = tid >> 2;
        int sh = (tid & 3) * 16;
        unsigned int c = 0;
        #pragma unroll
        for (int w = 0; w < 4; w++)
            c += (unsigned int)((warp_acc[w][q] >> sh) & 0xFFFFull);
        s_cnt[tid] = (float)c;

        int a = tid >> 2, b = tid & 3;
        float s = 1.0f / sqrtf(1.0f + EPSF);   // normalize(e_v) component
        float ra[3] = {0.f, 0.f, 0.f};
        float rb[3] = {0.f, 0.f, 0.f};
        if (a > 0) ra[a - 1] = s;
        if (b > 0) rb[b - 1] = s;
        #pragma unroll
        for (int k = 0; k < 3; k++) {
            s_dr2[tid][k] = rb[k] - ra[k];
            s_m2 [tid][k] = 0.5f * (rb[k] + ra[k]);
        }
    }
    __syncthreads();

    // =====================================================================
    // Phase 2: per-i contribution over the 16 groups
    // =====================================================================
    double dacc = 0.0;
    if (i < nseg) {
        const float TWO_PI = 6.283185307179586476925f;

        float t0 = (b0 / 255.0f) * TWO_PI;
        float t1 = (b1 / 255.0f) * TWO_PI;
        float s0, c0, s1, c1;
        sincosf(t0, &s0, &c0);
        sincosf(t1, &s1, &c1);

        float x0 = 0.5f * s0, y0 = 0.3f * s0, z0 = 0.2f * s0;
        float x1 = 0.5f * s1, y1 = 0.3f * s1, z1 = 0.2f * s1;
        float inv0 = rsqrtf(c0 * c0 + x0 * x0 + y0 * y0 + z0 * z0 + EPSF);
        float inv1 = rsqrtf(c1 * c1 + x1 * x1 + y1 * y1 + z1 * z1 + EPSF);
        x0 *= inv0; y0 *= inv0; z0 *= inv0;
        x1 *= inv1; y1 *= inv1; z1 *= inv1;

        float dx1 = x1 - x0, dy1 = y1 - y0, dz1 = z1 - z0;
        float mx1 = 0.5f * (x1 + x0), my1 = 0.5f * (y1 + y0), mz1 = 0.5f * (z1 + z0);

        #pragma unroll
        for (int g = 0; g < 16; g++) {
            float cnt = s_cnt[g];
            float ax = s_dr2[g][0], ay = s_dr2[g][1], az = s_dr2[g][2];
            float cx = dy1 * az - dz1 * ay;
            float cy = dz1 * ax - dx1 * az;
            float cz = dx1 * ay - dy1 * ax;
            float fx = mx1 - s_m2[g][0];
            float fy = my1 - s_m2[g][1];
            float fz = mz1 - s_m2[g][2];
            float num = cx * fx + cy * fy + cz * fz;
            float d2  = fx * fx + fy * fy + fz * fz + EPSF;
            float rin = rsqrtf(d2);                  // d2^-1.5 = rin^3
            dacc += (double)(cnt * (num * (rin * rin * rin)));
        }
    }

    // =====================================================================
    // Phase 3: deterministic block reduction (double)
    // =====================================================================
    __shared__ double sm[NTHR];
    sm[tid] = dacc;
    __syncthreads();
    #pragma unroll
    for (int off = NTHR / 2; off > 0; off >>= 1) {
        if (tid < off) sm[tid] += sm[tid + off];
        __syncthreads();
    }

    __shared__ bool amLast;
    if (tid == 0) {
        g_partial[blockIdx.x] = sm[0];
        __threadfence();
        unsigned int t = atomicInc(&g_ticket, NBLK - 1);  // wraps -> replayable
        amLast = (t == NBLK - 1);
    }
    __syncthreads();

    // =====================================================================
    // Phase 4: last block folds the 32 partials in fixed order
    // =====================================================================
    if (amLast && tid < 32) {
        double vv = g_partial[tid];
        #pragma unroll
        for (int off = 16; off > 0; off >>= 1)
            vv += __shfl_down_sync(0xffffffffu, vv, off);
        if (tid == 0)
            out[0] = (float)(vv / (4.0 * 3.14159265358979323846));
    }
}

extern "C" void kernel_launch(void* const* d_in, const int* in_sizes, int n_in,
                              void* d_out, int out_size)
{
    const float* bytes = (const float*)d_in[0];   // starcoder_bytes, 4096 f32
    const int*   idx   = (const int*)d_in[1];     // hg38_indices,   4096 i32
    float*       out   = (float*)d_out;

    int n = in_sizes[0];   // 4096

    braid_fused_kernel<<<NBLK, NTHR>>>(bytes, idx, n, out);
}

// round 6
// speedup vs baseline: 1.3204x; 1.3204x over previous
#include <cuda_runtime.h>
#include <math.h>

// GenomicLogicBraidIntegrator — single launch, dependency-free restructure.
//
// r2[j] takes only 4 distinct values -> (dr2[j], m2[j]) determined by
// (idx[j], idx[j+1]) -> 16 segment descriptors g. The O(N^2) Gauss linking
// sum collapses EXACTLY to:
//      sum_g cnt[g] * S[g],   S[g] = sum_i term(i, g)
// cnt[] depends only on idx, S[] only on bytes -> computed CONCURRENTLY,
// cross-multiplied once in the last-block fold. One thread per segment.
//
// (Resubmission of R5: the R5 bench failed with "device busy/unavailable"
// at harness device acquisition — infra transient, kernel never ran.)

#define EPSF 1e-9f
#define NBLK 32
#define NTHR 128

__device__ double             g_S[NBLK * 16];   // per-block S[g] partials
__device__ unsigned long long g_C[NBLK * 4];    // per-block packed histogram
__device__ unsigned int       g_ticket = 0;

__global__ void __launch_bounds__(NTHR)
braid_fused_kernel(const float* __restrict__ bytes,
                   const int*   __restrict__ idx,
                   int n, float* __restrict__ out)
{
    const int tid  = threadIdx.x;
    const int lane = tid & 31;
    const int wid  = tid >> 5;
    const int nseg = n - 1;                       // 4095
    const int i    = blockIdx.x * NTHR + tid;     // this thread's segment
    const bool act = (i < nseg);

    // ---- issue all global loads up front (overlapped) -------------------
    int   ia = act ? idx[i]     : 0;
    int   ib = act ? idx[i + 1] : 0;
    float b0 = act ? bytes[i]     : 0.0f;
    float b1 = act ? bytes[i + 1] : 0.0f;

    // ---- histogram side: packed counters, <=1 item per thread -----------
    unsigned long long h0 = 0, h1 = 0, h2 = 0, h3 = 0;
    if (act) {
        int g = (ia << 2) | ib;
        unsigned long long inc = 1ULL << ((g & 3) * 16);
        switch (g >> 2) {
            case 0: h0 = inc; break;
            case 1: h1 = inc; break;
            case 2: h2 = inc; break;
            default: h3 = inc; break;
        }
    }
    #pragma unroll
    for (int off = 16; off > 0; off >>= 1) {
        h0 += __shfl_down_sync(0xffffffffu, h0, off);
        h1 += __shfl_down_sync(0xffffffffu, h1, off);
        h2 += __shfl_down_sync(0xffffffffu, h2, off);
        h3 += __shfl_down_sync(0xffffffffu, h3, off);
    }

    // ---- term side: this segment's contribution to each of 16 groups ----
    float term[16];
    {
        const float TWO_PI = 6.283185307179586476925f;
        float t0 = (b0 / 255.0f) * TWO_PI;
        float t1 = (b1 / 255.0f) * TWO_PI;
        float s0, c0, s1, c1;
        sincosf(t0, &s0, &c0);
        sincosf(t1, &s1, &c1);

        float x0 = 0.5f * s0, y0 = 0.3f * s0, z0 = 0.2f * s0;
        float x1 = 0.5f * s1, y1 = 0.3f * s1, z1 = 0.2f * s1;
        float inv0 = rsqrtf(c0 * c0 + x0 * x0 + y0 * y0 + z0 * z0 + EPSF);
        float inv1 = rsqrtf(c1 * c1 + x1 * x1 + y1 * y1 + z1 * z1 + EPSF);
        x0 *= inv0; y0 *= inv0; z0 *= inv0;
        x1 *= inv1; y1 *= inv1; z1 *= inv1;

        float dx1 = x1 - x0, dy1 = y1 - y0, dz1 = z1 - z0;
        float mx1 = 0.5f * (x1 + x0), my1 = 0.5f * (y1 + y0), mz1 = 0.5f * (z1 + z0);

        const float sc = 1.0f / sqrtf(1.0f + EPSF);  // normalize(e_v) comp
        #pragma unroll
        for (int g = 0; g < 16; g++) {
            int a = g >> 2, b = g & 3;
            // dr2_g / m2_g as compile-time sparse vectors
            float ra0 = (a == 1) ? sc : 0.f, ra1 = (a == 2) ? sc : 0.f, ra2 = (a == 3) ? sc : 0.f;
            float rb0 = (b == 1) ? sc : 0.f, rb1 = (b == 2) ? sc : 0.f, rb2 = (b == 3) ? sc : 0.f;
            float ax = rb0 - ra0, ay = rb1 - ra1, az = rb2 - ra2;
            float ox = 0.5f * (rb0 + ra0), oy = 0.5f * (rb1 + ra1), oz = 0.5f * (rb2 + ra2);

            float cx = dy1 * az - dz1 * ay;
            float cy = dz1 * ax - dx1 * az;
            float cz = dx1 * ay - dy1 * ax;
            float fx = mx1 - ox, fy = my1 - oy, fz = mz1 - oz;
            float num = cx * fx + cy * fy + cz * fz;
            float d2  = fx * fx + fy * fy + fz * fz + EPSF;
            float rin = rsqrtf(d2);                   // d2^-1.5 = rin^3
            term[g] = act ? (num * (rin * rin * rin)) : 0.0f;
        }
    }

    // warp pairwise reduction of the 16 term sums (float, exact tree)
    #pragma unroll
    for (int off = 16; off > 0; off >>= 1) {
        #pragma unroll
        for (int g = 0; g < 16; g++)
            term[g] += __shfl_down_sync(0xffffffffu, term[g], off);
    }

    // ---- block combine: 4 warps -> per-block partials --------------------
    __shared__ float              s_S[4][16];
    __shared__ unsigned long long s_h[4][4];
    if (lane == 0) {
        #pragma unroll
        for (int g = 0; g < 16; g++) s_S[wid][g] = term[g];
        s_h[wid][0] = h0; s_h[wid][1] = h1; s_h[wid][2] = h2; s_h[wid][3] = h3;
    }
    __syncthreads();

    if (tid < 16) {
        double d = 0.0;
        #pragma unroll
        for (int w = 0; w < 4; w++) d += (double)s_S[w][tid];
        g_S[blockIdx.x * 16 + tid] = d;
    }
    if (tid < 4) {
        unsigned long long c = 0;
        #pragma unroll
        for (int w = 0; w < 4; w++) c += s_h[w][tid];
        g_C[blockIdx.x * 4 + tid] = c;
    }

    // ---- fenced ticket: last block folds everything ----------------------
    __shared__ bool amLast;
    __syncthreads();
    if (tid == 0) {
        __threadfence();
        unsigned int t = atomicInc(&g_ticket, NBLK - 1);  // wraps -> replayable
        amLast = (t == NBLK - 1);
    }
    __syncthreads();

    if (amLast && tid < 32) {
        double val = 0.0;
        if (tid < 16) {
            // S[g]: fixed-order fold over 32 block partials
            double S = 0.0;
            #pragma unroll
            for (int b = 0; b < NBLK; b++) S += g_S[b * 16 + tid];
            // cnt[g] from packed histogram quadrants
            int q = tid >> 2, sh = (tid & 3) * 16;
            unsigned int cnt = 0;
            #pragma unroll
            for (int b = 0; b < NBLK; b++)
                cnt += (unsigned int)((g_C[b * 4 + q] >> sh) & 0xFFFFull);
            val = (double)cnt * S;
        }
        #pragma unroll
        for (int off = 16; off > 0; off >>= 1)
            val += __shfl_down_sync(0xffffffffu, val, off);
        if (tid == 0)
            out[0] = (float)(val / (4.0 * 3.14159265358979323846));
    }
}

extern "C" void kernel_launch(void* const* d_in, const int* in_sizes, int n_in,
                              void* d_out, int out_size)
{
    const float* bytes = (const float*)d_in[0];   // starcoder_bytes, 4096 f32
    const int*   idx   = (const int*)d_in[1];     // hg38_indices,   4096 i32
    float*       out   = (float*)d_out;

    int n = in_sizes[0];   // 4096

    braid_fused_kernel<<<NBLK, NTHR>>>(bytes, idx, n, out);
}